// round 4
// baseline (speedup 1.0000x reference)
#include <cuda_runtime.h>
#include <math.h>

#define HW 65536
#define BATCH 4
#define NSEG 32
#define GCH 128
#define GPAD 140   // 140 % 32 == 12 -> conflict-free LDS.128 strides; 140 % 4 == 0 -> float4 aligned

// ---------------- static scratch (no allocations allowed) ----------------
__device__ float g_xn  [(size_t)BATCH * 96  * HW];   // LN output (reused for LN1 and LN2)
__device__ float g_qkv [(size_t)BATCH * 288 * HW];   // qkv pre-dwconv; later reused for gated FFN 'g'
__device__ float g_qkvd[(size_t)BATCH * 288 * HW];   // qkv post-dwconv (q|k|v)
__device__ float g_svpq[(size_t)BATCH * 12  * HW];   // svp_q
__device__ float g_pp  [(size_t)BATCH * 510 * HW];   // p1 (255) | p2 (255)
__device__ float g_ss  [BATCH * 204];                // sum-of-squares: 96 q, 96 k, 12 svp per batch
__device__ float g_gp  [NSEG * 16 * 648];            // Gram partials per segment
__device__ float g_M   [BATCH * 96 * 96];            // fused proj_out @ attn

// ---------------- f32x2 helpers ----------------
__device__ __forceinline__ unsigned long long pack2(float lo, float hi) {
    unsigned long long r;
    asm("mov.b64 %0, {%1, %2};" : "=l"(r) : "f"(lo), "f"(hi));
    return r;
}
__device__ __forceinline__ void unpack2(unsigned long long v, float& lo, float& hi) {
    asm("mov.b64 {%0, %1}, %2;" : "=f"(lo), "=f"(hi) : "l"(v));
}
__device__ __forceinline__ void fma2(unsigned long long& d, unsigned long long a, unsigned long long b) {
    asm("fma.rn.f32x2 %0, %1, %2, %0;" : "+l"(d) : "l"(a), "l"(b));
}

// ---------------- channel LayerNorm (over 96 channels per pixel) ----------------
__global__ void ln_kernel(const float* __restrict__ x, const float* __restrict__ w,
                          const float* __restrict__ bias, float* __restrict__ out) {
    int i = blockIdx.x * blockDim.x + threadIdx.x;
    if (i >= BATCH * HW) return;
    int b = i >> 16, pix = i & 65535;
    const float* xp = x + (long long)b * 96 * HW + pix;
    float sum = 0.f, sq = 0.f;
    #pragma unroll 8
    for (int c = 0; c < 96; c++) {
        float v = xp[(long long)c * HW];
        sum += v; sq += v * v;
    }
    float mu  = sum * (1.f / 96.f);
    float var = sq * (1.f / 96.f) - mu * mu;
    float inv = rsqrtf(var + 1e-5f);
    float* op = out + (long long)b * 96 * HW + pix;
    #pragma unroll 8
    for (int c = 0; c < 96; c++) {
        float v = xp[(long long)c * HW];
        op[(long long)c * HW] = (v - mu) * inv * w[c] + bias[c];
    }
}

// ---------------- GEMM: C[M,N=65536] = A[M,K] @ B[K,N] (+ optional residual) ----------------
// 128x128 tile, BK=8, 256 threads, 8x8 microtile as f32x2 pairs, double-buffered smem.
__global__ __launch_bounds__(256) void gemm_f32x2(
    const float* __restrict__ A, const float* __restrict__ B,
    const float* __restrict__ R, float* __restrict__ C,
    int M, int K,
    long long sA, long long sB, long long sR, long long sC, int resid)
{
    A += (long long)blockIdx.z * sA;
    B += (long long)blockIdx.z * sB;
    C += (long long)blockIdx.z * sC;
    if (resid) R += (long long)blockIdx.z * sR;

    const int m_base = blockIdx.y * 128;
    const int n_base = blockIdx.x * 128;
    const int tid = threadIdx.x;

    __shared__ float As[2][8][128];  // As[k][m] (transposed)
    __shared__ float Bs[2][8][128];

    const int row_a = tid >> 1;
    const int kq    = (tid & 1) * 4;
    const int krow  = tid >> 5;
    const int ncol  = (tid & 31) * 4;
    const int tx = tid & 15;
    const int ty = tid >> 4;

    unsigned long long acc[8][4];
    #pragma unroll
    for (int i = 0; i < 8; i++)
        #pragma unroll
        for (int j = 0; j < 4; j++) acc[i][j] = 0ULL;

    const int nstages = (K + 7) >> 3;

    float ra[4]; float4 rb;
    // prologue: fetch + store stage 0
    {
        #pragma unroll
        for (int i = 0; i < 4; i++) {
            int kk = kq + i;
            ra[i] = (m_base + row_a < M && kk < K) ? A[(long long)(m_base + row_a) * K + kk] : 0.f;
        }
        rb = (krow < K) ? *(const float4*)(B + (long long)krow * HW + n_base + ncol)
                        : make_float4(0.f, 0.f, 0.f, 0.f);
        #pragma unroll
        for (int i = 0; i < 4; i++) As[0][kq + i][row_a] = ra[i];
        *(float4*)&Bs[0][krow][ncol] = rb;
    }
    __syncthreads();

    for (int s = 0; s < nstages; s++) {
        int buf = s & 1;
        if (s + 1 < nstages) {
            int kg = (s + 1) * 8;
            #pragma unroll
            for (int i = 0; i < 4; i++) {
                int kk = kg + kq + i;
                ra[i] = (m_base + row_a < M && kk < K) ? A[(long long)(m_base + row_a) * K + kk] : 0.f;
            }
            int kb = kg + krow;
            rb = (kb < K) ? *(const float4*)(B + (long long)kb * HW + n_base + ncol)
                          : make_float4(0.f, 0.f, 0.f, 0.f);
        }
        #pragma unroll
        for (int kk = 0; kk < 8; kk++) {
            float4 a0 = *(const float4*)&As[buf][kk][ty * 4];
            float4 a1 = *(const float4*)&As[buf][kk][64 + ty * 4];
            float4 b0 = *(const float4*)&Bs[buf][kk][tx * 4];
            float4 b1 = *(const float4*)&Bs[buf][kk][64 + tx * 4];
            unsigned long long bb[4];
            bb[0] = pack2(b0.x, b0.y); bb[1] = pack2(b0.z, b0.w);
            bb[2] = pack2(b1.x, b1.y); bb[3] = pack2(b1.z, b1.w);
            float am[8] = {a0.x, a0.y, a0.z, a0.w, a1.x, a1.y, a1.z, a1.w};
            #pragma unroll
            for (int i = 0; i < 8; i++) {
                unsigned long long ad = pack2(am[i], am[i]);
                #pragma unroll
                for (int j = 0; j < 4; j++) fma2(acc[i][j], ad, bb[j]);
            }
        }
        if (s + 1 < nstages) {
            int nb = buf ^ 1;
            #pragma unroll
            for (int i = 0; i < 4; i++) As[nb][kq + i][row_a] = ra[i];
            *(float4*)&Bs[nb][krow][ncol] = rb;
        }
        __syncthreads();
    }

    #pragma unroll
    for (int i = 0; i < 8; i++) {
        int row = (i < 4) ? (ty * 4 + i) : (64 + ty * 4 + (i - 4));
        int mg = m_base + row;
        if (mg >= M) continue;
        float4 v0, v1;
        unpack2(acc[i][0], v0.x, v0.y); unpack2(acc[i][1], v0.z, v0.w);
        unpack2(acc[i][2], v1.x, v1.y); unpack2(acc[i][3], v1.z, v1.w);
        long long o0 = (long long)mg * HW + n_base + tx * 4;
        long long o1 = o0 + 64;
        if (resid) {
            float4 r0 = *(const float4*)(R + o0);
            float4 r1 = *(const float4*)(R + o1);
            v0.x += r0.x; v0.y += r0.y; v0.z += r0.z; v0.w += r0.w;
            v1.x += r1.x; v1.y += r1.y; v1.z += r1.z; v1.w += r1.w;
        }
        *(float4*)(C + o0) = v0;
        *(float4*)(C + o1) = v1;
    }
}

// ---------------- 3x3 depthwise conv, SAME zero padding ----------------
__global__ void dwconv3(const float* __restrict__ in, const float* __restrict__ w,
                        float* __restrict__ out) {
    int zc = blockIdx.z;                 // b*288 + c
    int c = zc % 288;
    const float* src = in  + (long long)zc * HW;
    float*       dst = out + (long long)zc * HW;
    int ox = blockIdx.x * 32, oy = blockIdx.y * 8;
    __shared__ float s[10][34];
    int tid = threadIdx.y * 32 + threadIdx.x;
    for (int i = tid; i < 340; i += 256) {
        int r = i / 34, cc = i % 34;
        int gy = oy + r - 1, gx = ox + cc - 1;
        float v = 0.f;
        if (gy >= 0 && gy < 256 && gx >= 0 && gx < 256) v = src[gy * 256 + gx];
        s[r][cc] = v;
    }
    __syncthreads();
    const float* wc = w + c * 9;
    float w00 = wc[0], w01 = wc[1], w02 = wc[2];
    float w10 = wc[3], w11 = wc[4], w12 = wc[5];
    float w20 = wc[6], w21 = wc[7], w22 = wc[8];
    int tx = threadIdx.x, ty = threadIdx.y;
    float r = w00 * s[ty][tx]     + w01 * s[ty][tx + 1]     + w02 * s[ty][tx + 2]
            + w10 * s[ty + 1][tx] + w11 * s[ty + 1][tx + 1] + w12 * s[ty + 1][tx + 2]
            + w20 * s[ty + 2][tx] + w21 * s[ty + 2][tx + 1] + w22 * s[ty + 2][tx + 2];
    dst[(oy + ty) * 256 + ox + tx] = r;
}

// ---------------- svp 1x1 conv: (12,3) @ (b,3,hw) ----------------
__global__ void svp_kernel(const float* __restrict__ fea, const float* __restrict__ w,
                           float* __restrict__ out) {
    int i = blockIdx.x * blockDim.x + threadIdx.x;
    if (i >= BATCH * HW) return;
    int b = i >> 16, pix = i & 65535;
    const float* f = fea + (long long)b * 3 * HW + pix;
    float f0 = f[0], f1 = f[HW], f2 = f[2 * HW];
    float* o = out + (long long)b * 12 * HW + pix;
    #pragma unroll
    for (int r = 0; r < 12; r++)
        o[(long long)r * HW] = w[r * 3] * f0 + w[r * 3 + 1] * f1 + w[r * 3 + 2] * f2;
}

// ---------------- per-row sum of squares (for L2 norms) ----------------
__global__ void sumsq_kernel(const float* __restrict__ qkvd, const float* __restrict__ svpq,
                             float* __restrict__ ss) {
    int bid = blockIdx.x;
    int b = bid / 204, r = bid % 204;
    const float* row = (r < 192) ? qkvd + ((long long)b * 288 + r) * HW
                                 : svpq + ((long long)b * 12 + (r - 192)) * HW;
    float acc = 0.f;
    for (int i = threadIdx.x * 4; i < HW; i += blockDim.x * 4) {
        float4 v = *(const float4*)(row + i);
        acc += v.x * v.x + v.y * v.y + v.z * v.z + v.w * v.w;
    }
    __shared__ float red[256];
    red[threadIdx.x] = acc;
    __syncthreads();
    for (int st = 128; st > 0; st >>= 1) {
        if (threadIdx.x < st) red[threadIdx.x] += red[threadIdx.x + st];
        __syncthreads();
    }
    if (threadIdx.x == 0) ss[bid] = red[0];
}

// ---------------- Gram: G[bh][27][24] partials over pixel segments ----------------
__global__ __launch_bounds__(672) void gram_kernel(const float* __restrict__ qkvd,
                                                   const float* __restrict__ svpq,
                                                   float* __restrict__ gp) {
    __shared__ float qs[27 * GPAD];
    __shared__ float ks[24 * GPAD];
    int seg = blockIdx.x;            // 0..31
    int bh  = blockIdx.y;            // 0..15
    int b = bh >> 2, h = bh & 3;
    int tid = threadIdx.x;
    int c = tid / 24, d = tid % 24;
    bool active = tid < 648;
    long long segoff = (long long)seg * (HW / NSEG);
    float acc = 0.f;

    for (int ch = 0; ch < HW / NSEG; ch += GCH) {
        for (int i = tid; i < 51 * (GCH / 4); i += 672) {
            int row = i / (GCH / 4), col4 = i % (GCH / 4);
            const float* src;
            float* dstb;
            if (row < 27) {
                src = (row < 24) ? qkvd + ((long long)b * 288 + h * 24 + row) * HW
                                 : svpq + ((long long)b * 12 + h * 3 + (row - 24)) * HW;
                dstb = qs + row * GPAD;
            } else {
                int rr = row - 27;
                src = qkvd + ((long long)b * 288 + 96 + h * 24 + rr) * HW;
                dstb = ks + rr * GPAD;
            }
            *(float4*)(dstb + col4 * 4) = *(const float4*)(src + segoff + ch + col4 * 4);
        }
        __syncthreads();
        if (active) {
            const float4* q4 = (const float4*)(qs + c * GPAD);
            const float4* k4 = (const float4*)(ks + d * GPAD);
            #pragma unroll 8
            for (int p = 0; p < GCH / 4; p++) {
                float4 qv = q4[p], kv = k4[p];
                acc += qv.x * kv.x + qv.y * kv.y + qv.z * kv.z + qv.w * kv.w;
            }
        }
        __syncthreads();
    }
    if (active) gp[((long long)seg * 16 + bh) * 648 + tid] = acc;
}

// ---------------- attn softmax + fuse proj_out into M[b] (96x96) ----------------
__global__ void attnm_kernel(const float* __restrict__ gp, const float* __restrict__ ss,
                             const float* __restrict__ temp, const float* __restrict__ projw,
                             float* __restrict__ Mout) {
    int b = blockIdx.x;
    __shared__ float attn_s[4][27][24];
    int tid = threadIdx.x;
    if (tid < 108) {
        int h = tid / 27, c = tid % 27;
        float ssq = (c < 24) ? ss[b * 204 + h * 24 + c]
                             : ss[b * 204 + 192 + h * 3 + (c - 24)];
        float nq = fmaxf(sqrtf(ssq), 1e-12f);
        float t = temp[h];
        float row[24];
        #pragma unroll
        for (int d = 0; d < 24; d++) {
            float g = 0.f;
            for (int s = 0; s < NSEG; s++)
                g += gp[((long long)s * 16 + b * 4 + h) * 648 + c * 24 + d];
            float nk = fmaxf(sqrtf(ss[b * 204 + 96 + h * 24 + d]), 1e-12f);
            row[d] = g * t / (nq * nk);
        }
        float mx = row[0];
        #pragma unroll
        for (int d = 1; d < 24; d++) mx = fmaxf(mx, row[d]);
        float sum = 0.f;
        #pragma unroll
        for (int d = 0; d < 24; d++) { row[d] = expf(row[d] - mx); sum += row[d]; }
        float inv = 1.f / sum;
        #pragma unroll
        for (int d = 0; d < 24; d++) attn_s[h][c][d] = row[d] * inv;
    }
    __syncthreads();
    for (int e = tid; e < 96 * 96; e += blockDim.x) {
        int o = e / 96, col = e % 96;
        int h = col / 24, d = col % 24;
        float s = 0.f;
        #pragma unroll
        for (int c = 0; c < 27; c++)
            s += projw[o * 108 + h * 27 + c] * attn_s[h][c][d];
        Mout[b * 9216 + e] = s;
    }
}

// ---------------- dual-gated FFN elementwise ----------------
__device__ __forceinline__ float gatef(float a, float bb) {
    float sig = 1.f / (1.f + expf(-bb));
    float gel = 0.5f * a * (1.f + erff(a * 0.70710678118654752f));
    return a * sig + bb * gel;
}
__global__ void gate_kernel(const float* __restrict__ pp, float* __restrict__ g) {
    long long i = ((long long)blockIdx.x * blockDim.x + threadIdx.x) * 4;
    const long long total = (long long)BATCH * 255 * HW;
    if (i >= total) return;
    long long b = i / (255LL * HW);
    long long rem = i % (255LL * HW);
    const float* p1p = pp + b * 510LL * HW + rem;
    const float* p2p = p1p + 255LL * HW;
    float4 p1 = *(const float4*)p1p;
    float4 p2 = *(const float4*)p2p;
    float4 r;
    r.x = gatef(p1.x, p2.x);
    r.y = gatef(p1.y, p2.y);
    r.z = gatef(p1.z, p2.z);
    r.w = gatef(p1.w, p2.w);
    *(float4*)(g + b * 288LL * HW + rem) = r;
}

// ---------------- launch ----------------
extern "C" void kernel_launch(void* const* d_in, const int* in_sizes, int n_in,
                              void* d_out, int out_size) {
    const float* x           = (const float*)d_in[0];
    const float* svp_fea     = (const float*)d_in[1];
    const float* n1w         = (const float*)d_in[2];
    const float* n1b         = (const float*)d_in[3];
    const float* qkv_w       = (const float*)d_in[4];
    const float* qkv_dw_w    = (const float*)d_in[5];
    const float* svp_w       = (const float*)d_in[6];
    const float* temperature = (const float*)d_in[7];
    const float* proj_out_w  = (const float*)d_in[8];
    const float* n2w         = (const float*)d_in[9];
    const float* n2b         = (const float*)d_in[10];
    const float* ffn1_w      = (const float*)d_in[11];
    const float* ffn2_w      = (const float*)d_in[12];
    const float* ffn_out_w   = (const float*)d_in[13];
    float* out = (float*)d_out;

    float *xn, *qkv, *qkvd, *svpq, *pp, *ss, *gp, *Mm;
    cudaGetSymbolAddress((void**)&xn,   g_xn);
    cudaGetSymbolAddress((void**)&qkv,  g_qkv);
    cudaGetSymbolAddress((void**)&qkvd, g_qkvd);
    cudaGetSymbolAddress((void**)&svpq, g_svpq);
    cudaGetSymbolAddress((void**)&pp,   g_pp);
    cudaGetSymbolAddress((void**)&ss,   g_ss);
    cudaGetSymbolAddress((void**)&gp,   g_gp);
    cudaGetSymbolAddress((void**)&Mm,   g_M);

    const int pixBlocks = (BATCH * HW + 255) / 256;

    // 1. LN1
    ln_kernel<<<pixBlocks, 256>>>(x, n1w, n1b, xn);
    // 2. qkv = Wqkv(288,96) @ xn
    gemm_f32x2<<<dim3(512, 3, BATCH), 256>>>(qkv_w, xn, nullptr, qkv,
        288, 96, 0, 96LL * HW, 0, 288LL * HW, 0);
    // 3. depthwise 3x3
    dwconv3<<<dim3(8, 32, BATCH * 288), dim3(32, 8)>>>(qkv, qkv_dw_w, qkvd);
    // 4. svp_q
    svp_kernel<<<pixBlocks, 256>>>(svp_fea, svp_w, svpq);
    // 5. row norms (sum of squares)
    sumsq_kernel<<<BATCH * 204, 256>>>(qkvd, svpq, ss);
    // 6. Gram partials
    gram_kernel<<<dim3(NSEG, 16), 672>>>(qkvd, svpq, gp);
    // 7. softmax + fold proj_out -> M[b] (96x96)
    attnm_kernel<<<BATCH, 128>>>(gp, ss, temperature, proj_out_w, Mm);
    // 8. x2 = x + M_b @ v   (v = qkvd rows 192..287), x2 stored in d_out
    gemm_f32x2<<<dim3(512, 1, BATCH), 256>>>(Mm, qkvd + 192LL * HW, x, out,
        96, 96, 9216, 288LL * HW, 96LL * HW, 96LL * HW, 1);
    // 9. LN2 (reads d_out) -> xn
    ln_kernel<<<pixBlocks, 256>>>(out, n2w, n2b, xn);
    // 10. p1, p2
    gemm_f32x2<<<dim3(512, 2, BATCH), 256>>>(ffn1_w, xn, nullptr, pp,
        255, 96, 0, 96LL * HW, 0, 510LL * HW, 0);
    gemm_f32x2<<<dim3(512, 2, BATCH), 256>>>(ffn2_w, xn, nullptr, pp + 255LL * HW,
        255, 96, 0, 96LL * HW, 0, 510LL * HW, 0);
    // 11. g = p1*sigmoid(p2) + p2*gelu(p1)  (stored in qkv buffer, stride 288 rows)
    gate_kernel<<<(int)(((long long)BATCH * 255 * HW / 4 + 255) / 256), 256>>>(pp, qkv);
    // 12. out = out + Wout(96,255) @ g
    gemm_f32x2<<<dim3(512, 1, BATCH), 256>>>(ffn_out_w, qkv, out, out,
        96, 255, 0, 288LL * HW, 96LL * HW, 96LL * HW, 1);
}